// round 6
// baseline (speedup 1.0000x reference)
#include <cuda_runtime.h>
#include <cuda_bf16.h>

// RandomShiftsAug collapsed to a single gather:
//   out[n,c,i,j] = x[n, c, wrap(max(ky+i-4,0)), clamp(kx+j-4,0,419)]
// x: (128, 9, 84, 420) fp32, shift: (128, 2) int32 (kx = shift[:,0], ky = shift[:,1])
// out: (128, 9, 84, 420) fp32
//
// Layout: one block per output row (grid 84 x 1152, 128 threads).
// Thread t covers columns {t, t+128, t+256, t+384}: every warp load is 32
// CONSECUTIVE floats (nL~1 line per LDG) instead of the R2 stride-4 gather
// (nL=4 per LDG) that saturated L1tex wavefronts at 57.7%.

#define N_CH 9
#define H 84
#define W 420

__global__ __launch_bounds__(128) void RandomShiftsAug_59115929862159_kernel(
    const float* __restrict__ x,
    const int2*  __restrict__ shift,       // shift[n] = (kx, ky)
    float*       __restrict__ out)
{
    const int i  = blockIdx.x;             // output row within image [0,84)
    const int nc = blockIdx.y;             // n*9 + c                  [0,1152)
    const int n  = nc / N_CH;

    const int2 s  = __ldg(&shift[n]);
    const int  dx = s.x - 4;               // column shift in [-4, 4]

    // source row: wrap(max(ky + i - 4, 0)); ky+i-4 in [-4, 87]
    int r = s.y + i - 4;
    r = max(r, 0);
    if (r >= H) r -= H;                    // <= 87, one subtract wraps the tile

    const float* src = x   + ((size_t)nc * H + r) * W;
    float*       dst = out + ((size_t)nc * H + i) * W;

    const int t  = threadIdx.x;
    const int j0 = t;                      // [0,128)
    const int j1 = t + 128;                // [128,256)
    const int j2 = t + 256;                // [256,384)
    const int j3 = t + 384;                // [384,512) -> active only < 420

    // Clamp analysis: j0+dx in [-4,131] -> lower clamp only.
    //                 j1+dx, j2+dx in [124,387] -> no clamp needed.
    //                 j3+dx in [380,423] -> upper clamp only.
    const int c0 = max(j0 + dx, 0);
    const int c1 = j1 + dx;
    const int c2 = j2 + dx;
    const int c3 = min(j3 + dx, W - 1);

    // Front-batched independent loads (MLP=4), streaming hints (single-touch).
    float v0 = __ldcs(src + c0);
    float v1 = __ldcs(src + c1);
    float v2 = __ldcs(src + c2);
    float v3 = 0.0f;
    const bool tail = (j3 < W);
    if (tail) v3 = __ldcs(src + c3);

    __stcs(dst + j0, v0);
    __stcs(dst + j1, v1);
    __stcs(dst + j2, v2);
    if (tail) __stcs(dst + j3, v3);
}

extern "C" void kernel_launch(void* const* d_in, const int* in_sizes, int n_in,
                              void* d_out, int out_size)
{
    const float* x     = (const float*)d_in[0];
    const int2*  shift = (const int2*)d_in[1];
    float*       out   = (float*)d_out;

    dim3 grid(H, 128 * N_CH);              // (84, 1152) blocks, one per row
    RandomShiftsAug_59115929862159_kernel<<<grid, 128>>>(x, shift, out);
}